// round 12
// baseline (speedup 1.0000x reference)
#include <cuda_runtime.h>
#include <math.h>

// Problem constants
#define B_  2
#define W_  4096
#define R_  8
#define D_  32
#define C_  64                 // chunk length
#define NC_ (W_ / C_)          // 64 chunks
#define GRID_ (B_ * NC_)       // 128 blocks (<= 148 SMs: all co-resident)

// Scratch + flags (device globals — no allocation allowed)
__device__ float g_L[B_ * NC_ * R_ * D_];             // per-chunk local sums
__device__ __align__(16) unsigned g_flag[B_][NC_];    // epoch flags (monotone)

// ---------------------------------------------------------------------------
// Fused kernel. One block per (b, chunk). 512 threads, 1 block/SM, one wave.
//  Phase A: L_c[r,d] = gamma^63 * sum_j kg[r][j] h[j][d]   (kg = k*gamma^-j)
//  publish: fence; g_flag[b][c] = E+1  (plain release store; E = entry epoch)
//  overlap: A[i][j] = sum_r qg[i][r] kg[r][j]  (j<=i else 0), AND the whole
//           intra-chunk A·h accumulation (doesn't need g_L)
//  wait:    tight poll of g_flag[b][0..c) >= E+1 (point-to-point, no RMW)
//  post:    Sin via 4 independent Horner chains; add inter-chunk term; store.
// Epoch flags are monotone across graph replays: no reset, no RMW.
// ---------------------------------------------------------------------------
__global__ void __launch_bounds__(512, 1)
k_fused(const float* __restrict__ qin, const float* __restrict__ kin,
        const float* __restrict__ hin, const float* __restrict__ gamma,
        float* __restrict__ out)
{
    const int blk = blockIdx.x;
    const int b = blk >> 6, c = blk & 63;
    const int w0 = c * C_;
    const int t = threadIdx.x;

    __shared__ float hs  [C_][D_];
    __shared__ float kgT [R_][C_];
    __shared__ float qg  [C_][R_];
    __shared__ float A   [C_][C_ + 4];
    __shared__ float Sin [R_][D_];
    __shared__ float Pbuf[R_][D_];
    __shared__ float pwp [R_][C_ + 1];   // gamma_r^j, j=0..64
    __shared__ float pwn [R_][C_];       // gamma_r^-j
    __shared__ float gam_s[R_];

    // ---- 1. issue global loads FIRST (registers; longest latency) ----
    float4 hreg, kqreg;
    hreg = ((const float4*)(hin + (size_t)(b * W_ + w0) * D_))[t];
    if (t < 128)
        kqreg = ((const float4*)(kin + (size_t)(b * W_ + w0) * R_))[t];
    else if (t < 256)
        kqreg = ((const float4*)(qin + (size_t)(b * W_ + w0) * R_))[t - 128];

    // entry epoch (t0): flags are uniform across blocks at every launch start
    unsigned E = 0;
    if (t == 0) {
        asm volatile("ld.relaxed.gpu.global.u32 %0, [%1];"
                     : "=r"(E) : "l"(&g_flag[b][c]) : "memory");
    }

    // ---- 2. power tables, fully parallel (512 threads -> one (r,j) each) ----
    {
        const int r = t >> 6, j = t & 63;
        const float lg = __log2f(__ldg(&gamma[r]));
        const float fj = (float)j;
        pwp[r][j] = exp2f(fj * lg);
        pwn[r][j] = exp2f(-fj * lg);
        if (t < 8) {
            gam_s[t]   = __ldg(&gamma[t]);
            pwp[t][C_] = exp2f(64.f * __log2f(__ldg(&gamma[t])));
        }
    }
    ((float4*)hs)[t] = hreg;
    __syncthreads();

    // ---- 3. prescale k/q into shared via table lookups ----
    if (t < 128) {
        int j = t >> 1, r0 = (t & 1) * 4;
        kgT[r0 + 0][j] = kqreg.x * pwn[r0 + 0][j];
        kgT[r0 + 1][j] = kqreg.y * pwn[r0 + 1][j];
        kgT[r0 + 2][j] = kqreg.z * pwn[r0 + 2][j];
        kgT[r0 + 3][j] = kqreg.w * pwn[r0 + 3][j];
    } else if (t < 256) {
        int tt = t - 128;
        int i = tt >> 1, r0 = (tt & 1) * 4;
        qg[i][r0 + 0] = kqreg.x * pwp[r0 + 0][i];
        qg[i][r0 + 1] = kqreg.y * pwp[r0 + 1][i];
        qg[i][r0 + 2] = kqreg.z * pwp[r0 + 2][i];
        qg[i][r0 + 3] = kqreg.w * pwp[r0 + 3][i];
    }
    __syncthreads();

    // ---- Phase A: local decayed sums (512 threads: (half, r, d)) ----
    {
        const int d = t & 31, r = (t >> 5) & 7, half = t >> 8;
        const int j0 = half << 5;
        float a0 = 0.f, a1 = 0.f;
#pragma unroll
        for (int m = 0; m < 16; ++m) {
            a0 = fmaf(kgT[r][j0 + 2 * m],     hs[j0 + 2 * m][d],     a0);
            a1 = fmaf(kgT[r][j0 + 2 * m + 1], hs[j0 + 2 * m + 1][d], a1);
        }
        float part = a0 + a1;
        if (half == 0) Pbuf[r][d] = part;
        __syncthreads();
        if (half == 1) {
            g_L[((b * NC_ + c) * R_ + r) * D_ + d] = pwp[r][63] * (part + Pbuf[r][d]);
        }
    }
    __syncthreads();

    // ---- publish: release g_L via epoch flag (plain store, no RMW) ----
    if (t == 0) {
        __threadfence();
        asm volatile("st.relaxed.gpu.global.u32 [%0], %1;"
                     :: "l"(&g_flag[b][c]), "r"(E + 1) : "memory");
    }

    // ---- Stage 1: A matrix (independent of g_L — overlaps other blocks) ----
    {
        const int i1 = t >> 3;            // 0..63
        const int jb = t & 7;             // 0..7
        float qr[8];
#pragma unroll
        for (int r = 0; r < 8; ++r) qr[r] = qg[i1][r];
#pragma unroll
        for (int jj = 0; jj < 8; ++jj) {
            const int j = jb + jj * 8;
            float a = 0.f;
#pragma unroll
            for (int r = 0; r < 8; ++r) a = fmaf(qr[r], kgT[r][j], a);
            A[i1][j] = (j <= i1) ? a : 0.f;
        }
    }
    __syncthreads();                      // A visible block-wide

    // ---- Stage 2a: intra-chunk A·h accumulation (still in overlap window) ----
    const int w = t >> 5;                 // 0..15
    const int d2 = t & 31;
    const int r0 = w, r1 = 31 - w;        // rows with len <= 32
    const int r2 = 32 + w, r3 = 63 - w;   // rows with len <= 64
    float acc0 = 0.f, acc1 = 0.f, acc2 = 0.f, acc3 = 0.f;
    {
#pragma unroll
        for (int j4 = 0; j4 < 32; j4 += 4) {
            const float4 a0 = *(const float4*)&A[r0][j4];
            const float4 a1 = *(const float4*)&A[r1][j4];
            const float h0 = hs[j4 + 0][d2], h1 = hs[j4 + 1][d2];
            const float h2 = hs[j4 + 2][d2], h3 = hs[j4 + 3][d2];
            acc0 = fmaf(a0.x, h0, acc0); acc0 = fmaf(a0.y, h1, acc0);
            acc0 = fmaf(a0.z, h2, acc0); acc0 = fmaf(a0.w, h3, acc0);
            acc1 = fmaf(a1.x, h0, acc1); acc1 = fmaf(a1.y, h1, acc1);
            acc1 = fmaf(a1.z, h2, acc1); acc1 = fmaf(a1.w, h3, acc1);
        }
#pragma unroll
        for (int j4 = 0; j4 < 64; j4 += 4) {
            const float4 a2 = *(const float4*)&A[r2][j4];
            const float4 a3 = *(const float4*)&A[r3][j4];
            const float h0 = hs[j4 + 0][d2], h1 = hs[j4 + 1][d2];
            const float h2 = hs[j4 + 2][d2], h3 = hs[j4 + 3][d2];
            acc2 = fmaf(a2.x, h0, acc2); acc2 = fmaf(a2.y, h1, acc2);
            acc2 = fmaf(a2.z, h2, acc2); acc2 = fmaf(a2.w, h3, acc2);
            acc3 = fmaf(a3.x, h0, acc3); acc3 = fmaf(a3.y, h1, acc3);
            acc3 = fmaf(a3.z, h2, acc3); acc3 = fmaf(a3.w, h3, acc3);
        }
    }

    // ---- wait: tight poll, only flags < c (point-to-point, no RMW) ----
    if (t == 0 && c > 0) {
        const unsigned target = E + 1;
        const unsigned* fp = &g_flag[b][0];
        bool ok;
        do {
            ok = true;
#pragma unroll 4
            for (int i0 = 0; i0 < c; i0 += 4) {
                uint4 f;
                asm volatile("ld.relaxed.gpu.global.v4.u32 {%0,%1,%2,%3}, [%4];"
                             : "=r"(f.x), "=r"(f.y), "=r"(f.z), "=r"(f.w)
                             : "l"(fp + i0) : "memory");
                if ((int)(f.x - target) < 0) ok = false;
                if (i0 + 1 < c && (int)(f.y - target) < 0) ok = false;
                if (i0 + 2 < c && (int)(f.z - target) < 0) ok = false;
                if (i0 + 3 < c && (int)(f.w - target) < 0) ok = false;
            }
        } while (!ok);
        __threadfence();                  // acquire before g_L reads
    }
    __syncthreads();

    // ---- Sin: 4 independent Horner chains (ratio gamma^256) -> 4x MLP ----
    if (t < 256) {
        const int r = t >> 5, dd = t & 31;
        float s = 0.f;
        if (c > 0) {
            const float gC  = pwp[r][C_];       // gamma^64
            const float gC2 = gC * gC;
            const float gC4 = gC2 * gC2;
            const float* Lp = g_L + (size_t)b * NC_ * R_ * D_ + r * D_ + dd;
            // s = sum_{e=0}^{c-1} gC^e * L[c-1-e];  split e by (e mod 4)
            float a0 = 0.f, a1 = 0.f, a2 = 0.f, a3 = 0.f;
            const int nmax = (c + 3) >> 2;
            for (int u = nmax - 1; u >= 0; --u) {
                const int e0 = 4 * u;
                if (e0 + 0 < c) a0 = fmaf(gC4, a0, __ldcg(Lp + (size_t)(c - 1 - e0)     * (R_ * D_)));
                if (e0 + 1 < c) a1 = fmaf(gC4, a1, __ldcg(Lp + (size_t)(c - 2 - e0)     * (R_ * D_)));
                if (e0 + 2 < c) a2 = fmaf(gC4, a2, __ldcg(Lp + (size_t)(c - 3 - e0)     * (R_ * D_)));
                if (e0 + 3 < c) a3 = fmaf(gC4, a3, __ldcg(Lp + (size_t)(c - 4 - e0)     * (R_ * D_)));
            }
            s = fmaf(gC, a1, a0) + gC2 * fmaf(gC, a3, a2);
        }
        Sin[r][dd] = s;
    }
    __syncthreads();

    // ---- Stage 2b: add inter-chunk term, store ----
    {
#pragma unroll
        for (int r = 0; r < 8; ++r) {
            const float gs = gam_s[r];
            const float sv = Sin[r][d2];
            acc0 = fmaf(qg[r0][r] * gs, sv, acc0);
            acc1 = fmaf(qg[r1][r] * gs, sv, acc1);
            acc2 = fmaf(qg[r2][r] * gs, sv, acc2);
            acc3 = fmaf(qg[r3][r] * gs, sv, acc3);
        }
        float* ob = out + (size_t)(b * W_ + w0) * D_ + d2;
        ob[(size_t)r0 * D_] = acc0;
        ob[(size_t)r1 * D_] = acc1;
        ob[(size_t)r2 * D_] = acc2;
        ob[(size_t)r3 * D_] = acc3;
    }
    // no reset needed: epoch flags are monotone across graph replays
}

// ---------------------------------------------------------------------------
// Launch. Inputs (metadata order):
//   0: q_alpha [B,W,R]  1: k [B,W,R]  2: h_norm [B,W,D]
//   3: gamma_vec [R]    4: causal_mask (unused)  5: decay_diff (unused)
// out: float32 [B,W,D]
// ---------------------------------------------------------------------------
extern "C" void kernel_launch(void* const* d_in, const int* in_sizes, int n_in,
                              void* d_out, int out_size)
{
    const float* q     = (const float*)d_in[0];
    const float* k     = (const float*)d_in[1];
    const float* h     = (const float*)d_in[2];
    const float* gamma = (const float*)d_in[3];
    float* out         = (float*)d_out;

    k_fused<<<GRID_, 512>>>(q, k, h, gamma, out);
}

// round 13
// speedup vs baseline: 1.4681x; 1.4681x over previous
#include <cuda_runtime.h>
#include <math.h>

// Problem constants
#define B_  2
#define W_  4096
#define R_  8
#define D_  32
#define C_  64                 // chunk length
#define NC_ (W_ / C_)          // 64 chunks
#define GRID_ (B_ * NC_)       // 128 blocks (<= 148 SMs: all co-resident)

// Scratch + barrier state (device globals — no allocation allowed)
__device__ float g_L[B_ * NC_ * R_ * D_];   // per-chunk local decayed sums
__device__ unsigned g_bar  = 0;             // grid barrier arrivals
__device__ unsigned g_done = 0;             // completion counter (for reset)

// ---------------------------------------------------------------------------
// Fused kernel (Round-8 structure, 12.4us baseline; single change: Sin is
// parity-split across all 512 threads instead of 256-thread pairwise Horner).
//  Phase A: L_c[r,d] = gamma^63 * sum_j kg[r][j] h[j][d]   (kg = k*gamma^-j)
//  arrive:  fence + atomicAdd(g_bar)
//  overlap: A[i][j] = sum_r qg[i][r] kg[r][j]  (j<=i else 0)
//  wait:    t0 polls ld.acquire(g_bar) == GRID (no RMW contention)
//  Phase B: Sin = decayed sum of previous chunks' L; out = A·h + q·gamma·Sin
// ---------------------------------------------------------------------------
__global__ void __launch_bounds__(512, 1)
k_fused(const float* __restrict__ qin, const float* __restrict__ kin,
        const float* __restrict__ hin, const float* __restrict__ gamma,
        float* __restrict__ out)
{
    const int blk = blockIdx.x;
    const int b = blk / NC_, c = blk % NC_;
    const int w0 = c * C_;
    const int t = threadIdx.x;

    __shared__ float hs  [C_][D_];        // h chunk
    __shared__ float kgT [R_][C_];        // k * gamma^{-j}, transposed
    __shared__ float qg  [C_][R_];        // q * gamma^{i}
    __shared__ float A   [C_][C_ + 4];    // padded rows
    __shared__ float Sin [R_][D_];
    __shared__ float Pbuf[R_][D_];
    __shared__ float gam_s[R_];

    // ---- loads (float4) + decay pre-scaling ----
    {
        const float4* h4 = (const float4*)(hin + (size_t)(b * W_ + w0) * D_);
        ((float4*)hs)[t] = h4[t];         // 512 float4 = full 64x32 tile
    }
    if (t < 8) gam_s[t] = gamma[t];
    if (t < 128) {                        // k: 128 float4, transpose + gamma^-j
        const float4* k4 = (const float4*)(kin + (size_t)(b * W_ + w0) * R_);
        float4 v = k4[t];
        int j = t >> 1, r0 = (t & 1) * 4;
        float fj = -(float)j;
        kgT[r0 + 0][j] = v.x * exp2f(fj * __log2f(__ldg(&gamma[r0 + 0])));
        kgT[r0 + 1][j] = v.y * exp2f(fj * __log2f(__ldg(&gamma[r0 + 1])));
        kgT[r0 + 2][j] = v.z * exp2f(fj * __log2f(__ldg(&gamma[r0 + 2])));
        kgT[r0 + 3][j] = v.w * exp2f(fj * __log2f(__ldg(&gamma[r0 + 3])));
    } else if (t < 256) {                 // q: 128 float4, gamma^+i
        const float4* q4 = (const float4*)(qin + (size_t)(b * W_ + w0) * R_);
        int tt = t - 128;
        float4 v = q4[tt];
        int j = tt >> 1, r0 = (tt & 1) * 4;
        float fj = (float)j;
        qg[j][r0 + 0] = v.x * exp2f(fj * __log2f(__ldg(&gamma[r0 + 0])));
        qg[j][r0 + 1] = v.y * exp2f(fj * __log2f(__ldg(&gamma[r0 + 1])));
        qg[j][r0 + 2] = v.z * exp2f(fj * __log2f(__ldg(&gamma[r0 + 2])));
        qg[j][r0 + 3] = v.w * exp2f(fj * __log2f(__ldg(&gamma[r0 + 3])));
    }
    __syncthreads();

    // ---- Phase A: local decayed sums (512 threads: (half, r, d)) ----
    {
        const int d = t & 31, r = (t >> 5) & 7, half = t >> 8;
        const int j0 = half << 5;
        float a0 = 0.f, a1 = 0.f;
#pragma unroll
        for (int m = 0; m < 16; ++m) {
            a0 = fmaf(kgT[r][j0 + 2 * m],     hs[j0 + 2 * m][d],     a0);
            a1 = fmaf(kgT[r][j0 + 2 * m + 1], hs[j0 + 2 * m + 1][d], a1);
        }
        float part = a0 + a1;
        if (half == 0) Pbuf[r][d] = part;
        __syncthreads();
        if (half == 1) {
            float g63 = exp2f(63.f * __log2f(gam_s[r]));
            g_L[((b * NC_ + c) * R_ + r) * D_ + d] = g63 * (part + Pbuf[r][d]);
        }
    }
    __syncthreads();

    // ---- barrier arrive: fence-release then relaxed atomic (t0 only) ----
    if (t == 0) {
        __threadfence();
        atomicAdd(&g_bar, 1u);
    }

    // ---- Stage 1: A matrix (independent of g_L — overlaps other blocks) ----
    {
        const int i1 = t >> 3;            // 0..63
        const int jb = t & 7;             // 0..7
        float qr[8];
#pragma unroll
        for (int r = 0; r < 8; ++r) qr[r] = qg[i1][r];
#pragma unroll
        for (int jj = 0; jj < 8; ++jj) {
            const int j = jb + jj * 8;    // lanes hit consecutive j: no conflicts
            float a = 0.f;
#pragma unroll
            for (int r = 0; r < 8; ++r) a = fmaf(qr[r], kgT[r][j], a);
            A[i1][j] = (j <= i1) ? a : 0.f;
        }
    }
    __syncthreads();

    // ---- barrier wait: ACQUIRE-LOAD polling of one counter (no RMW) ----
    if (t == 0 && c > 0) {
        unsigned v;
        do {
            asm volatile("ld.acquire.gpu.global.u32 %0, [%1];"
                         : "=r"(v) : "l"(&g_bar) : "memory");
        } while (v < (unsigned)GRID_);
    }
    __syncthreads();

    // ---- Sin: parity-split over 512 threads (chain depth <=32, 2x MLP) ----
    // half p handles chunks cp == p (mod 2): s_p = sum gC^{cpmax_p - cp} L[cp]
    // Sin = w0*s_0 + w1*s_1, w_p = 1 if p == (c-1)&1 else gC.
    {
        const int p  = t >> 8;            // 0 or 1
        const int rd = t & 255;
        const int r = rd >> 5, dd = rd & 31;
        const float gC  = exp2f(64.f * __log2f(gam_s[r]));   // gamma^64
        const float gC2 = gC * gC;
        const float* Lp = g_L + (size_t)b * NC_ * R_ * D_ + r * D_ + dd;
        float s = 0.f;
#pragma unroll 4
        for (int cp = p; cp < c; cp += 2)
            s = fmaf(gC2, s, __ldcg(Lp + (size_t)cp * (R_ * D_)));
        const float wgt = (((c - 1) & 1) == p) ? 1.f : gC;
        if (p == 0) Pbuf[r][dd] = s * wgt;
        __syncthreads();
        if (p == 1) Sin[r][dd] = fmaf(s, wgt, Pbuf[r][dd]);
    }
    __syncthreads();

    // ---- Stage 2: 16 warps; pair-split balanced rows, float4 A broadcasts ----
    {
        const int w = t >> 5;             // 0..15
        const int d = t & 31;
        const int r0 = w, r1 = 31 - w;      // rows with len <= 32
        const int r2 = 32 + w, r3 = 63 - w; // rows with len <= 64

        float acc0 = 0.f, acc1 = 0.f, acc2 = 0.f, acc3 = 0.f;

#pragma unroll
        for (int j4 = 0; j4 < 32; j4 += 4) {   // pair 1
            const float4 a0 = *(const float4*)&A[r0][j4];
            const float4 a1 = *(const float4*)&A[r1][j4];
            const float h0 = hs[j4 + 0][d], h1 = hs[j4 + 1][d];
            const float h2 = hs[j4 + 2][d], h3 = hs[j4 + 3][d];
            acc0 = fmaf(a0.x, h0, acc0); acc0 = fmaf(a0.y, h1, acc0);
            acc0 = fmaf(a0.z, h2, acc0); acc0 = fmaf(a0.w, h3, acc0);
            acc1 = fmaf(a1.x, h0, acc1); acc1 = fmaf(a1.y, h1, acc1);
            acc1 = fmaf(a1.z, h2, acc1); acc1 = fmaf(a1.w, h3, acc1);
        }
#pragma unroll
        for (int j4 = 0; j4 < 64; j4 += 4) {   // pair 2
            const float4 a2 = *(const float4*)&A[r2][j4];
            const float4 a3 = *(const float4*)&A[r3][j4];
            const float h0 = hs[j4 + 0][d], h1 = hs[j4 + 1][d];
            const float h2 = hs[j4 + 2][d], h3 = hs[j4 + 3][d];
            acc2 = fmaf(a2.x, h0, acc2); acc2 = fmaf(a2.y, h1, acc2);
            acc2 = fmaf(a2.z, h2, acc2); acc2 = fmaf(a2.w, h3, acc2);
            acc3 = fmaf(a3.x, h0, acc3); acc3 = fmaf(a3.y, h1, acc3);
            acc3 = fmaf(a3.z, h2, acc3); acc3 = fmaf(a3.w, h3, acc3);
        }

        // inter-chunk term: sum_r qg[i][r] * gamma_r * Sin[r][d]
#pragma unroll
        for (int r = 0; r < 8; ++r) {
            const float gs = gam_s[r];
            const float sv = Sin[r][d];
            acc0 = fmaf(qg[r0][r] * gs, sv, acc0);
            acc1 = fmaf(qg[r1][r] * gs, sv, acc1);
            acc2 = fmaf(qg[r2][r] * gs, sv, acc2);
            acc3 = fmaf(qg[r3][r] * gs, sv, acc3);
        }

        float* ob = out + (size_t)(b * W_ + w0) * D_ + d;
        ob[(size_t)r0 * D_] = acc0;
        ob[(size_t)r1 * D_] = acc1;
        ob[(size_t)r2 * D_] = acc2;
        ob[(size_t)r3 * D_] = acc3;
    }

    // ---- reset barrier state for next graph replay ----
    __syncthreads();
    if (t == 0) {
        unsigned v = atomicAdd(&g_done, 1u);
        if (v == (unsigned)(GRID_ - 1)) {
            atomicExch(&g_bar, 0u);
            atomicExch(&g_done, 0u);
        }
    }
}

// ---------------------------------------------------------------------------
// Launch. Inputs (metadata order):
//   0: q_alpha [B,W,R]  1: k [B,W,R]  2: h_norm [B,W,D]
//   3: gamma_vec [R]    4: causal_mask (unused)  5: decay_diff (unused)
// out: float32 [B,W,D]
// ---------------------------------------------------------------------------
extern "C" void kernel_launch(void* const* d_in, const int* in_sizes, int n_in,
                              void* d_out, int out_size)
{
    const float* q     = (const float*)d_in[0];
    const float* k     = (const float*)d_in[1];
    const float* h     = (const float*)d_in[2];
    const float* gamma = (const float*)d_in[3];
    float* out         = (float*)d_out;

    k_fused<<<GRID_, 512>>>(q, k, h, gamma, out);
}

// round 14
// speedup vs baseline: 1.5973x; 1.0880x over previous
#include <cuda_runtime.h>
#include <math.h>

// Problem constants
#define B_  2
#define W_  4096
#define R_  8
#define D_  32
#define C_  64                 // chunk length
#define NC_ (W_ / C_)          // 64 chunks
#define GRID_ (B_ * NC_)       // 128 blocks (<= 148 SMs: all co-resident)

// Scratch + barrier state (device globals — no allocation allowed)
__device__ float g_L[B_ * NC_ * R_ * D_];   // per-chunk local decayed sums
__device__ unsigned g_bar = 0;              // monotone arrival counter (never reset)

// ---------------------------------------------------------------------------
// Fused kernel (R8/R13 skeleton). One block per (b, chunk), 512 thr, 1/SM.
//  Phase A: L_c[r,d] = gamma^63 * sum_j kg[r][j] h[j][d]   (kg = k*gamma^-j)
//  arrive:  fence + atomicAdd(g_bar)   [monotone across graph replays]
//  overlap: A[i][j] = sum_r qg[i][r] kg[r][j]  AND full A·h accumulation
//  wait:    t0 polls ld.acquire(g_bar) >= (E/GRID+1)*GRID  (E = entry read,
//           taken BEFORE own arrival -> floor(E/GRID) = launch index)
//  post:    parity-split Sin; += q*gamma*Sin; store.  NO exit reset chain.
// ---------------------------------------------------------------------------
__global__ void __launch_bounds__(512, 1)
k_fused(const float* __restrict__ qin, const float* __restrict__ kin,
        const float* __restrict__ hin, const float* __restrict__ gamma,
        float* __restrict__ out)
{
    const int blk = blockIdx.x;
    const int b = blk / NC_, c = blk % NC_;
    const int w0 = c * C_;
    const int t = threadIdx.x;

    __shared__ float hs  [C_][D_];        // h chunk
    __shared__ float kgT [R_][C_];        // k * gamma^{-j}, transposed
    __shared__ float qg  [C_][R_];        // q * gamma^{i}
    __shared__ float A   [C_][C_ + 4];    // padded rows
    __shared__ float Sin [R_][D_];
    __shared__ float Pbuf[R_][D_];
    __shared__ float gam_s[R_];

    // ---- entry epoch read (t0, BEFORE arriving; monotone counter) ----
    unsigned E = 0;
    if (t == 0) {
        asm volatile("ld.relaxed.gpu.global.u32 %0, [%1];"
                     : "=r"(E) : "l"(&g_bar) : "memory");
    }

    // ---- loads (float4) + decay pre-scaling ----
    {
        const float4* h4 = (const float4*)(hin + (size_t)(b * W_ + w0) * D_);
        ((float4*)hs)[t] = h4[t];         // 512 float4 = full 64x32 tile
    }
    if (t < 8) gam_s[t] = gamma[t];
    if (t < 128) {                        // k: 128 float4, transpose + gamma^-j
        const float4* k4 = (const float4*)(kin + (size_t)(b * W_ + w0) * R_);
        float4 v = k4[t];
        int j = t >> 1, r0 = (t & 1) * 4;
        float fj = -(float)j;
        kgT[r0 + 0][j] = v.x * exp2f(fj * __log2f(__ldg(&gamma[r0 + 0])));
        kgT[r0 + 1][j] = v.y * exp2f(fj * __log2f(__ldg(&gamma[r0 + 1])));
        kgT[r0 + 2][j] = v.z * exp2f(fj * __log2f(__ldg(&gamma[r0 + 2])));
        kgT[r0 + 3][j] = v.w * exp2f(fj * __log2f(__ldg(&gamma[r0 + 3])));
    } else if (t < 256) {                 // q: 128 float4, gamma^+i
        const float4* q4 = (const float4*)(qin + (size_t)(b * W_ + w0) * R_);
        int tt = t - 128;
        float4 v = q4[tt];
        int j = tt >> 1, r0 = (tt & 1) * 4;
        float fj = (float)j;
        qg[j][r0 + 0] = v.x * exp2f(fj * __log2f(__ldg(&gamma[r0 + 0])));
        qg[j][r0 + 1] = v.y * exp2f(fj * __log2f(__ldg(&gamma[r0 + 1])));
        qg[j][r0 + 2] = v.z * exp2f(fj * __log2f(__ldg(&gamma[r0 + 2])));
        qg[j][r0 + 3] = v.w * exp2f(fj * __log2f(__ldg(&gamma[r0 + 3])));
    }
    __syncthreads();

    // ---- Phase A: local decayed sums (512 threads: (half, r, d)) ----
    {
        const int d = t & 31, r = (t >> 5) & 7, half = t >> 8;
        const int j0 = half << 5;
        float a0 = 0.f, a1 = 0.f;
#pragma unroll
        for (int m = 0; m < 16; ++m) {
            a0 = fmaf(kgT[r][j0 + 2 * m],     hs[j0 + 2 * m][d],     a0);
            a1 = fmaf(kgT[r][j0 + 2 * m + 1], hs[j0 + 2 * m + 1][d], a1);
        }
        float part = a0 + a1;
        if (half == 0) Pbuf[r][d] = part;
        __syncthreads();
        if (half == 1) {
            float g63 = exp2f(63.f * __log2f(gam_s[r]));
            g_L[((b * NC_ + c) * R_ + r) * D_ + d] = g63 * (part + Pbuf[r][d]);
        }
    }
    __syncthreads();

    // ---- barrier arrive: fence-release then relaxed atomic (t0 only) ----
    if (t == 0) {
        __threadfence();
        atomicAdd(&g_bar, 1u);
    }

    // ---- Stage 1: A matrix (independent of g_L — overlaps other blocks) ----
    {
        const int i1 = t >> 3;            // 0..63
        const int jb = t & 7;             // 0..7
        float qr[8];
#pragma unroll
        for (int r = 0; r < 8; ++r) qr[r] = qg[i1][r];
#pragma unroll
        for (int jj = 0; jj < 8; ++jj) {
            const int j = jb + jj * 8;    // lanes hit consecutive j: no conflicts
            float a = 0.f;
#pragma unroll
            for (int r = 0; r < 8; ++r) a = fmaf(qr[r], kgT[r][j], a);
            A[i1][j] = (j <= i1) ? a : 0.f;
        }
    }
    __syncthreads();                      // A visible block-wide

    // ---- Stage 2a: intra-chunk A·h into registers (still overlap window) ----
    const int w2 = t >> 5;                // 0..15
    const int d2 = t & 31;
    const int r0 = w2, r1 = 31 - w2;      // rows with len <= 32
    const int r2 = 32 + w2, r3 = 63 - w2; // rows with len <= 64
    float acc0 = 0.f, acc1 = 0.f, acc2 = 0.f, acc3 = 0.f;
    {
#pragma unroll
        for (int j4 = 0; j4 < 32; j4 += 4) {
            const float4 a0 = *(const float4*)&A[r0][j4];
            const float4 a1 = *(const float4*)&A[r1][j4];
            const float h0 = hs[j4 + 0][d2], h1 = hs[j4 + 1][d2];
            const float h2 = hs[j4 + 2][d2], h3 = hs[j4 + 3][d2];
            acc0 = fmaf(a0.x, h0, acc0); acc0 = fmaf(a0.y, h1, acc0);
            acc0 = fmaf(a0.z, h2, acc0); acc0 = fmaf(a0.w, h3, acc0);
            acc1 = fmaf(a1.x, h0, acc1); acc1 = fmaf(a1.y, h1, acc1);
            acc1 = fmaf(a1.z, h2, acc1); acc1 = fmaf(a1.w, h3, acc1);
        }
#pragma unroll
        for (int j4 = 0; j4 < 64; j4 += 4) {
            const float4 a2 = *(const float4*)&A[r2][j4];
            const float4 a3 = *(const float4*)&A[r3][j4];
            const float h0 = hs[j4 + 0][d2], h1 = hs[j4 + 1][d2];
            const float h2 = hs[j4 + 2][d2], h3 = hs[j4 + 3][d2];
            acc2 = fmaf(a2.x, h0, acc2); acc2 = fmaf(a2.y, h1, acc2);
            acc2 = fmaf(a2.z, h2, acc2); acc2 = fmaf(a2.w, h3, acc2);
            acc3 = fmaf(a3.x, h0, acc3); acc3 = fmaf(a3.y, h1, acc3);
            acc3 = fmaf(a3.z, h2, acc3); acc3 = fmaf(a3.w, h3, acc3);
        }
    }

    // ---- barrier wait: ACQUIRE-LOAD poll of one counter; launch-invariant
    //      target = (floor(E/GRID)+1)*GRID  (no reset needed, monotone) ----
    if (t == 0 && c > 0) {
        const unsigned target = (E / (unsigned)GRID_ + 1u) * (unsigned)GRID_;
        unsigned v;
        do {
            asm volatile("ld.acquire.gpu.global.u32 %0, [%1];"
                         : "=r"(v) : "l"(&g_bar) : "memory");
        } while ((int)(v - target) < 0);
    }
    __syncthreads();

    // ---- Sin: parity-split over 512 threads (chain depth <=32, 2x MLP) ----
    {
        const int p  = t >> 8;            // 0 or 1
        const int rd = t & 255;
        const int r = rd >> 5, dd = rd & 31;
        const float gC  = exp2f(64.f * __log2f(gam_s[r]));   // gamma^64
        const float gC2 = gC * gC;
        const float* Lp = g_L + (size_t)b * NC_ * R_ * D_ + r * D_ + dd;
        float s = 0.f;
#pragma unroll 4
        for (int cp = p; cp < c; cp += 2)
            s = fmaf(gC2, s, __ldcg(Lp + (size_t)cp * (R_ * D_)));
        const float wgt = (((c - 1) & 1) == p) ? 1.f : gC;
        if (p == 0) Pbuf[r][dd] = s * wgt;
        __syncthreads();
        if (p == 1) Sin[r][dd] = fmaf(s, wgt, Pbuf[r][dd]);
    }
    __syncthreads();

    // ---- Stage 2b: add inter-chunk term, store ----
    {
#pragma unroll
        for (int r = 0; r < 8; ++r) {
            const float gs = gam_s[r];
            const float sv = Sin[r][d2];
            acc0 = fmaf(qg[r0][r] * gs, sv, acc0);
            acc1 = fmaf(qg[r1][r] * gs, sv, acc1);
            acc2 = fmaf(qg[r2][r] * gs, sv, acc2);
            acc3 = fmaf(qg[r3][r] * gs, sv, acc3);
        }
        float* ob = out + (size_t)(b * W_ + w0) * D_ + d2;
        ob[(size_t)r0 * D_] = acc0;
        ob[(size_t)r1 * D_] = acc1;
        ob[(size_t)r2 * D_] = acc2;
        ob[(size_t)r3 * D_] = acc3;
    }
    // no reset, no g_done: g_bar is monotone across graph replays
}

// ---------------------------------------------------------------------------
// Launch. Inputs (metadata order):
//   0: q_alpha [B,W,R]  1: k [B,W,R]  2: h_norm [B,W,D]
//   3: gamma_vec [R]    4: causal_mask (unused)  5: decay_diff (unused)
// out: float32 [B,W,D]
// ---------------------------------------------------------------------------
extern "C" void kernel_launch(void* const* d_in, const int* in_sizes, int n_in,
                              void* d_out, int out_size)
{
    const float* q     = (const float*)d_in[0];
    const float* k     = (const float*)d_in[1];
    const float* h     = (const float*)d_in[2];
    const float* gamma = (const float*)d_in[3];
    float* out         = (float*)d_out;

    k_fused<<<GRID_, 512>>>(q, k, h, gamma, out);
}

// round 15
// speedup vs baseline: 1.7066x; 1.0684x over previous
#include <cuda_runtime.h>
#include <math.h>

// Problem constants
#define B_  2
#define W_  4096
#define R_  8
#define D_  32
#define C_  64                 // chunk length
#define NC_ (W_ / C_)          // 64 chunks
#define GRID_ (B_ * NC_)       // 128 blocks (<= 148 SMs: all co-resident)

// Scratch + barrier state (device globals — no allocation allowed)
__device__ float g_L[B_ * NC_ * R_ * D_];   // per-chunk local decayed sums
// per-batch monotone arrival counters, padded to separate 128B lines
struct __align__(128) PadCtr { unsigned v; unsigned pad[31]; };
__device__ PadCtr g_barb[B_];               // never reset (monotone)

// ---------------------------------------------------------------------------
// Fused kernel (R14 skeleton + per-batch barrier + merged stage-2a loop).
//  Phase A: L_c[r,d] = gamma^63 * sum_j kg[r][j] h[j][d]   (kg = k*gamma^-j)
//  arrive:  fence + atomicAdd(g_barb[b])   [monotone across graph replays]
//  overlap: A[i][j] = sum_r qg[i][r] kg[r][j]  AND full A·h accumulation
//  wait:    t0 polls ld.acquire(g_barb[b]) >= (E/NC+1)*NC  (E read pre-arrive)
//  post:    parity-split Sin; += q*gamma*Sin; store.  No reset chain.
// ---------------------------------------------------------------------------
__global__ void __launch_bounds__(512, 1)
k_fused(const float* __restrict__ qin, const float* __restrict__ kin,
        const float* __restrict__ hin, const float* __restrict__ gamma,
        float* __restrict__ out)
{
    const int blk = blockIdx.x;
    const int b = blk / NC_, c = blk % NC_;
    const int w0 = c * C_;
    const int t = threadIdx.x;

    __shared__ float hs  [C_][D_];        // h chunk
    __shared__ float kgT [R_][C_];        // k * gamma^{-j}, transposed
    __shared__ float qg  [C_][R_];        // q * gamma^{i}
    __shared__ float A   [C_][C_ + 4];    // padded rows
    __shared__ float Sin [R_][D_];
    __shared__ float Pbuf[R_][D_];
    __shared__ float gam_s[R_];

    // ---- entry epoch read (t0, BEFORE arriving; own batch counter) ----
    unsigned E = 0;
    if (t == 0) {
        asm volatile("ld.relaxed.gpu.global.u32 %0, [%1];"
                     : "=r"(E) : "l"(&g_barb[b].v) : "memory");
    }

    // ---- loads (float4) + decay pre-scaling ----
    {
        const float4* h4 = (const float4*)(hin + (size_t)(b * W_ + w0) * D_);
        ((float4*)hs)[t] = h4[t];         // 512 float4 = full 64x32 tile
    }
    if (t < 8) gam_s[t] = gamma[t];
    if (t < 128) {                        // k: 128 float4, transpose + gamma^-j
        const float4* k4 = (const float4*)(kin + (size_t)(b * W_ + w0) * R_);
        float4 v = k4[t];
        int j = t >> 1, r0 = (t & 1) * 4;
        float fj = -(float)j;
        kgT[r0 + 0][j] = v.x * exp2f(fj * __log2f(__ldg(&gamma[r0 + 0])));
        kgT[r0 + 1][j] = v.y * exp2f(fj * __log2f(__ldg(&gamma[r0 + 1])));
        kgT[r0 + 2][j] = v.z * exp2f(fj * __log2f(__ldg(&gamma[r0 + 2])));
        kgT[r0 + 3][j] = v.w * exp2f(fj * __log2f(__ldg(&gamma[r0 + 3])));
    } else if (t < 256) {                 // q: 128 float4, gamma^+i
        const float4* q4 = (const float4*)(qin + (size_t)(b * W_ + w0) * R_);
        int tt = t - 128;
        float4 v = q4[tt];
        int j = tt >> 1, r0 = (tt & 1) * 4;
        float fj = (float)j;
        qg[j][r0 + 0] = v.x * exp2f(fj * __log2f(__ldg(&gamma[r0 + 0])));
        qg[j][r0 + 1] = v.y * exp2f(fj * __log2f(__ldg(&gamma[r0 + 1])));
        qg[j][r0 + 2] = v.z * exp2f(fj * __log2f(__ldg(&gamma[r0 + 2])));
        qg[j][r0 + 3] = v.w * exp2f(fj * __log2f(__ldg(&gamma[r0 + 3])));
    }
    __syncthreads();

    // ---- Phase A: local decayed sums (512 threads: (half, r, d)) ----
    {
        const int d = t & 31, r = (t >> 5) & 7, half = t >> 8;
        const int j0 = half << 5;
        float a0 = 0.f, a1 = 0.f;
#pragma unroll
        for (int m = 0; m < 16; ++m) {
            a0 = fmaf(kgT[r][j0 + 2 * m],     hs[j0 + 2 * m][d],     a0);
            a1 = fmaf(kgT[r][j0 + 2 * m + 1], hs[j0 + 2 * m + 1][d], a1);
        }
        float part = a0 + a1;
        if (half == 0) Pbuf[r][d] = part;
        __syncthreads();
        if (half == 1) {
            float g63 = exp2f(63.f * __log2f(gam_s[r]));
            g_L[((b * NC_ + c) * R_ + r) * D_ + d] = g63 * (part + Pbuf[r][d]);
        }
    }
    __syncthreads();

    // ---- barrier arrive: fence-release then relaxed atomic (t0 only) ----
    if (t == 0) {
        __threadfence();
        atomicAdd(&g_barb[b].v, 1u);
    }

    // ---- Stage 1: A matrix (independent of g_L — overlaps other blocks) ----
    {
        const int i1 = t >> 3;            // 0..63
        const int jb = t & 7;             // 0..7
        float qr[8];
#pragma unroll
        for (int r = 0; r < 8; ++r) qr[r] = qg[i1][r];
#pragma unroll
        for (int jj = 0; jj < 8; ++jj) {
            const int j = jb + jj * 8;    // lanes hit consecutive j: no conflicts
            float a = 0.f;
#pragma unroll
            for (int r = 0; r < 8; ++r) a = fmaf(qr[r], kgT[r][j], a);
            A[i1][j] = (j <= i1) ? a : 0.f;
        }
    }
    __syncthreads();                      // A visible block-wide

    // ---- Stage 2a: intra-chunk A·h into registers (overlap window).
    //      Single j loop: each hs[j][d] loaded ONCE, feeds all 4 rows.
    const int w2 = t >> 5;                // 0..15
    const int d2 = t & 31;
    const int r0 = w2, r1 = 31 - w2;      // rows with len <= 32
    const int r2 = 32 + w2, r3 = 63 - w2; // rows with len <= 64
    float acc0 = 0.f, acc1 = 0.f, acc2 = 0.f, acc3 = 0.f;
    {
#pragma unroll
        for (int j4 = 0; j4 < 64; j4 += 4) {
            const float h0 = hs[j4 + 0][d2], h1 = hs[j4 + 1][d2];
            const float h2 = hs[j4 + 2][d2], h3 = hs[j4 + 3][d2];
            const float4 a2 = *(const float4*)&A[r2][j4];
            const float4 a3 = *(const float4*)&A[r3][j4];
            acc2 = fmaf(a2.x, h0, acc2); acc2 = fmaf(a2.y, h1, acc2);
            acc2 = fmaf(a2.z, h2, acc2); acc2 = fmaf(a2.w, h3, acc2);
            acc3 = fmaf(a3.x, h0, acc3); acc3 = fmaf(a3.y, h1, acc3);
            acc3 = fmaf(a3.z, h2, acc3); acc3 = fmaf(a3.w, h3, acc3);
            if (j4 < 32) {                // compile-time under full unroll
                const float4 a0 = *(const float4*)&A[r0][j4];
                const float4 a1 = *(const float4*)&A[r1][j4];
                acc0 = fmaf(a0.x, h0, acc0); acc0 = fmaf(a0.y, h1, acc0);
                acc0 = fmaf(a0.z, h2, acc0); acc0 = fmaf(a0.w, h3, acc0);
                acc1 = fmaf(a1.x, h0, acc1); acc1 = fmaf(a1.y, h1, acc1);
                acc1 = fmaf(a1.z, h2, acc1); acc1 = fmaf(a1.w, h3, acc1);
            }
        }
    }

    // ---- barrier wait: ACQUIRE-LOAD poll of own batch counter;
    //      launch-invariant target = (floor(E/NC)+1)*NC (monotone) ----
    if (t == 0 && c > 0) {
        const unsigned target = (E / (unsigned)NC_ + 1u) * (unsigned)NC_;
        unsigned v;
        do {
            asm volatile("ld.acquire.gpu.global.u32 %0, [%1];"
                         : "=r"(v) : "l"(&g_barb[b].v) : "memory");
        } while ((int)(v - target) < 0);
    }
    __syncthreads();

    // ---- Sin: parity-split over 512 threads (chain depth <=32, 2x MLP) ----
    {
        const int p  = t >> 8;            // 0 or 1
        const int rd = t & 255;
        const int r = rd >> 5, dd = rd & 31;
        const float gC  = exp2f(64.f * __log2f(gam_s[r]));   // gamma^64
        const float gC2 = gC * gC;
        const float* Lp = g_L + (size_t)b * NC_ * R_ * D_ + r * D_ + dd;
        float s = 0.f;
#pragma unroll 4
        for (int cp = p; cp < c; cp += 2)
            s = fmaf(gC2, s, __ldcg(Lp + (size_t)cp * (R_ * D_)));
        const float wgt = (((c - 1) & 1) == p) ? 1.f : gC;
        if (p == 0) Pbuf[r][dd] = s * wgt;
        __syncthreads();
        if (p == 1) Sin[r][dd] = fmaf(s, wgt, Pbuf[r][dd]);
    }
    __syncthreads();

    // ---- Stage 2b: add inter-chunk term, store ----
    {
#pragma unroll
        for (int r = 0; r < 8; ++r) {
            const float gs = gam_s[r];
            const float sv = Sin[r][d2];
            acc0 = fmaf(qg[r0][r] * gs, sv, acc0);
            acc1 = fmaf(qg[r1][r] * gs, sv, acc1);
            acc2 = fmaf(qg[r2][r] * gs, sv, acc2);
            acc3 = fmaf(qg[r3][r] * gs, sv, acc3);
        }
        float* ob = out + (size_t)(b * W_ + w0) * D_ + d2;
        ob[(size_t)r0 * D_] = acc0;
        ob[(size_t)r1 * D_] = acc1;
        ob[(size_t)r2 * D_] = acc2;
        ob[(size_t)r3 * D_] = acc3;
    }
    // no reset: per-batch counters are monotone across graph replays
}

// ---------------------------------------------------------------------------
// Launch. Inputs (metadata order):
//   0: q_alpha [B,W,R]  1: k [B,W,R]  2: h_norm [B,W,D]
//   3: gamma_vec [R]    4: causal_mask (unused)  5: decay_diff (unused)
// out: float32 [B,W,D]
// ---------------------------------------------------------------------------
extern "C" void kernel_launch(void* const* d_in, const int* in_sizes, int n_in,
                              void* d_out, int out_size)
{
    const float* q     = (const float*)d_in[0];
    const float* k     = (const float*)d_in[1];
    const float* h     = (const float*)d_in[2];
    const float* gamma = (const float*)d_in[3];
    float* out         = (float*)d_out;

    k_fused<<<GRID_, 512>>>(q, k, h, gamma, out);
}